// round 17
// baseline (speedup 1.0000x reference)
#include <cuda_runtime.h>
#include <cstdint>
#include <math.h>

#define BB 64
#define TT 512
#define DD 256
#define HH 256
#define KK 512
#define NTHR 256
#define NBLK 256
#define NB_N 8         // hidden dims per block
#define NB_B 16        // batches per block
#define NGRP 8         // sync groups (dir x bgrp)
#define GRPBLK 32      // blocks per sync group

// ---------------- device scratch (static allocation, allowed) ----------------
__device__ float g_xt[2][TT][4][DD][NB_B];      // [dir][t][bgrp][k][b] non-dup (64 MB)
__device__ float g_hb[2][2][4][HH][NB_B];       // [dir][phase][bgrp][n][b] non-dup
__device__ int      g_flag[NGRP][GRPBLK][32];   // step flags, one 128B line each
__device__ unsigned g_bcnt, g_bsns;             // global barrier (self-stable)

// ---- fast gate math (|rel err| ~1e-6, saturation-safe) ----
__device__ __forceinline__ float fsig(float v) {
    return __fdividef(1.f, 1.f + __expf(-v));
}
__device__ __forceinline__ float ftanh(float v) {
    return 1.f - __fdividef(2.f, __expf(2.f * v) + 1.f);
}

// ---- packed fp32x2 helpers (sm_100+) ----
__device__ __forceinline__ void fmaf2(unsigned long long& d,
                                      unsigned long long a, unsigned long long b) {
    asm("fma.rn.f32x2 %0, %1, %2, %3;" : "=l"(d) : "l"(a), "l"(b), "l"(d));
}
__device__ __forceinline__ unsigned long long addf2(unsigned long long a,
                                                    unsigned long long b) {
    unsigned long long r;
    asm("add.rn.f32x2 %0, %1, %2;" : "=l"(r) : "l"(a), "l"(b));
    return r;
}
__device__ __forceinline__ void unpack2(unsigned long long v, float& lo, float& hi) {
    asm("mov.b64 {%0, %1}, %2;" : "=f"(lo), "=f"(hi) : "l"(v));
}
__device__ __forceinline__ unsigned long long pack2(float lo, float hi) {
    unsigned long long r;
    asm("mov.b64 %0, {%1, %2};" : "=l"(r) : "f"(lo), "f"(hi));
    return r;
}

// ---- release/acquire flag ops ----
__device__ __forceinline__ void st_release(int* p, int v) {
    asm volatile("st.release.gpu.global.b32 [%0], %1;" :: "l"(p), "r"(v) : "memory");
}
__device__ __forceinline__ int ld_acquire(const int* p) {
    int v;
    asm volatile("ld.acquire.gpu.global.b32 %0, [%1];" : "=r"(v) : "l"(p) : "memory");
    return v;
}

// ---- mbarrier + bulk-copy helpers (single-instruction 16KB transfers) ----
#define MBAR_INIT(addr, cnt) \
    asm volatile("mbarrier.init.shared.b64 [%0], %1;" :: "r"(addr), "r"(cnt) : "memory")
#define MBAR_EXPECT(addr, bytes) \
    asm volatile("mbarrier.arrive.expect_tx.shared.b64 _, [%0], %1;" \
                 :: "r"(addr), "r"(bytes) : "memory")
__device__ __forceinline__ void mbar_wait(uint32_t addr, uint32_t parity) {
    uint32_t done;
    asm volatile(
        "{\n\t.reg .pred p;\n\t"
        "mbarrier.try_wait.parity.shared.b64 p, [%1], %2;\n\t"
        "selp.b32 %0, 1, 0, p;\n\t}"
        : "=r"(done) : "r"(addr), "r"(parity) : "memory");
    while (!done) {
        asm volatile(
            "{\n\t.reg .pred p;\n\t"
            "mbarrier.try_wait.parity.shared.b64 p, [%1], %2, 0x989680;\n\t"
            "selp.b32 %0, 1, 0, p;\n\t}"
            : "=r"(done) : "r"(addr), "r"(parity) : "memory");
    }
}
__device__ __forceinline__ void bulk_g2s(uint32_t dst, const void* src,
                                         uint32_t bytes, uint32_t mbar) {
    asm volatile(
        "cp.async.bulk.shared::cta.global.mbarrier::complete_tx::bytes "
        "[%0], [%1], %2, [%3];"
        :: "r"(dst), "l"(src), "r"(bytes), "r"(mbar) : "memory");
}

__device__ __forceinline__ uint32_t smem_u32(const void* p) {
    uint32_t a;
    asm("{ .reg .u64 t; cvta.to.shared.u64 t, %1; cvt.u32.u64 %0, t; }"
        : "=r"(a) : "l"(p));
    return a;
}

__device__ __forceinline__ void global_barrier(int tid) {
    __syncthreads();
    if (tid == 0) {
        unsigned s0 = *((volatile unsigned*)&g_bsns);
        __threadfence();
        unsigned a = atomicAdd(&g_bcnt, 1u);
        if (a == NBLK - 1) {
            atomicExch(&g_bcnt, 0u);
            __threadfence();
            atomicExch(&g_bsns, s0 ^ 1u);
        } else {
            while (*((volatile unsigned*)&g_bsns) == s0) {}
        }
        __threadfence();
    }
    __syncthreads();
}

// SMEM float offsets (total ~112.4 KB -> 2 blocks/SM)
#define WT_F    0                       // [512][32]  64 KB weight rows (prologue tile aliases)
#define HX_F    (KK * 32)               // [512][16]  32 KB  ([x ; h] non-dup operand)
#define RED_F   (HX_F + KK * 16)        // u64[8*8*2][16] = 16 KB
#define BSV_F   (RED_F + 4096)          // [32]
#define SLEN_F  (BSV_F + 32)            // [64]
#define MB_F    (SLEN_F + 64)           // 2 x u64 mbarriers
#define SMEM_FLOATS (MB_F + 4)

// Inner GEMM: N k-steps, thread tile = 1 row-group (4 gates of dim nl) x 4 batches.
// Per k: 1 w LDS.128 + 1 h LDS.128 + 4 alu pack-movs + 8 FFMA2 = 16 MACs.
template <int N>
__device__ __forceinline__ void gemm_phase(unsigned long long* acc,
                                           const float* __restrict__ hp,
                                           const float* __restrict__ wp) {
    #pragma unroll 8
    for (int kk = 0; kk < N; ++kk) {
        ulonglong2 w = *(const ulonglong2*)(wp + kk * 32);     // (i,f),(g,o) of dim nl
        float4 h4 = *(const float4*)(hp + kk * 16);            // b0..b3
        unsigned long long hA0 = pack2(h4.x, h4.x);
        unsigned long long hA1 = pack2(h4.y, h4.y);
        unsigned long long hB0 = pack2(h4.z, h4.z);
        unsigned long long hB1 = pack2(h4.w, h4.w);
        fmaf2(acc[0], w.x, hA0); fmaf2(acc[1], w.x, hA1);
        fmaf2(acc[2], w.x, hB0); fmaf2(acc[3], w.x, hB1);
        fmaf2(acc[4], w.y, hA0); fmaf2(acc[5], w.y, hA1);
        fmaf2(acc[6], w.y, hB0); fmaf2(acc[7], w.y, hB1);
    }
}

extern "C" __global__ void __launch_bounds__(NTHR, 2)
bilstm_kernel(const float* __restrict__ x,
              const int*   __restrict__ lens,
              const float* __restrict__ Wih_f, const float* __restrict__ Whh_f,
              const float* __restrict__ bih_f, const float* __restrict__ bhh_f,
              const float* __restrict__ Wih_b, const float* __restrict__ Whh_b,
              const float* __restrict__ bih_b, const float* __restrict__ bhh_b,
              float* __restrict__ out)
{
    extern __shared__ float smem[];
    float* wt = smem + WT_F;                // [512][32] weight rows, r = nl*4+g
    float* hx = smem + HX_F;                // [512][16] staged [x ; h], non-dup
    unsigned long long* red = (unsigned long long*)(smem + RED_F);
    float* bsv  = smem + BSV_F;
    int*   slen = (int*)(smem + SLEN_F);
    float* tile = wt;                       // prologue transpose tile [256][65] (alias wt+hx)

    const uint32_t hx_b  = smem_u32(hx);
    const uint32_t mbx_b = smem_u32(smem + MB_F);       // x-tile mbarrier
    const uint32_t mbh_b = mbx_b + 8;                   // h-tile mbarrier

    const int tid  = threadIdx.x;
    const int dir  = blockIdx.x >> 7;           // 0..1
    const int bgrp = (blockIdx.x >> 5) & 3;     // 0..3
    const int nc   = blockIdx.x & 31;           // 0..31 (8 dims each)
    const int gid  = blockIdx.x >> 5;           // sync group 0..7

    const float* Wih = dir ? Wih_b : Wih_f;
    const float* Whh = dir ? Whh_b : Whh_f;
    const float* bih = dir ? bih_b : bih_f;
    const float* bhh = dir ? bhh_b : bhh_f;

    // ---------------- prologue ----------------
    if (tid < BB) slen[tid] = lens[tid];
    __syncthreads();

    // transpose x -> g_xt[dir_pro][t][bgrp][k][16] (non-dup); 128 blocks per dir stride t
    {
        const int dir_pro = blockIdx.x >> 7;
        const int idx128  = blockIdx.x & 127;
        const int bq  = tid >> 2;
        const int kq4 = tid & 3;
        for (int s = idx128; s < TT; s += 128) {
            int t;
            if (dir_pro == 0) t = s;
            else              t = TT - 1 - ((TT - slen[bq] + s) % TT);
            const float* xrow = x + ((size_t)bq * TT + t) * DD;
            #pragma unroll
            for (int kk = 0; kk < 16; ++kk) {
                int k0 = kq4 * 64 + kk * 4;
                float4 v = *(const float4*)(xrow + k0);
                tile[(k0 + 0) * 65 + bq] = v.x;
                tile[(k0 + 1) * 65 + bq] = v.y;
                tile[(k0 + 2) * 65 + bq] = v.z;
                tile[(k0 + 3) * 65 + bq] = v.w;
            }
            __syncthreads();
            const int k2 = tid;
            #pragma unroll
            for (int bg4 = 0; bg4 < 4; ++bg4) {
                float* dst = &g_xt[dir_pro][s][bg4][k2][0];
                #pragma unroll
                for (int q = 0; q < 4; ++q) {
                    float4 o;
                    o.x = tile[k2 * 65 + bg4 * 16 + q * 4 + 0];
                    o.y = tile[k2 * 65 + bg4 * 16 + q * 4 + 1];
                    o.z = tile[k2 * 65 + bg4 * 16 + q * 4 + 2];
                    o.w = tile[k2 * 65 + bg4 * 16 + q * 4 + 3];
                    *(float4*)(dst + q * 4) = o;
                }
            }
            __syncthreads();
        }
    }

    // weight slice: wt[k][r], r = nl*4 + g (gate order i,f,g,o), dims nc*8 + nl
    for (int idx = tid; idx < KK * 32; idx += NTHR) {
        int k = idx >> 5, r = idx & 31;
        int nl = r >> 2, g = r & 3;
        int j = g * HH + nc * NB_N + nl;
        wt[idx] = (k < DD) ? Wih[(size_t)j * DD + k] : Whh[(size_t)j * HH + (k - DD)];
    }
    if (tid < 32) {
        int nl = tid >> 2, g = tid & 3;
        int j = g * HH + nc * NB_N + nl;
        bsv[tid] = bih[j] + bhh[j];
    }
    // zero all h buffers (cooperative across all blocks; exactly one elem/thread)
    {
        float* hb = &g_hb[0][0][0][0][0];
        const int total = 2 * 2 * 4 * HH * NB_B;
        for (int i = blockIdx.x * NTHR + tid; i < total; i += NBLK * NTHR) hb[i] = 0.f;
    }
    if (tid == 0) {
        MBAR_INIT(mbx_b, 1);
        MBAR_INIT(mbh_b, 1);
    }
    __syncthreads();
    if (tid == 0) st_release(&g_flag[gid][nc][0], 1);   // h(0) ready

    global_barrier(tid);

    // prime x(0): single bulk copy, 16 KB
    if (tid == 0) {
        MBAR_EXPECT(mbx_b, 16384u);
        bulk_g2s(hx_b, &g_xt[dir][0][bgrp][0][0], 16384u, mbx_b);
    }

    // ---------------- recurrence ----------------
    // gemm map: warp = k-group (kq8 = 0..7, 32 k each half); lane -> (nl 0..7, bgq 0..3)
    const int kq8 = tid >> 5;
    const int lane = tid & 31;
    const int nl  = lane >> 2;
    const int bgq = lane & 3;
    // epilogue map: threads 0..127 own one (dim, batch) cell each
    const int e   = (tid & 127) >> 4;       // dim 0..7
    const int eb  = tid & 15;               // batch 0..15
    const int n   = nc * NB_N + e;
    const int myb = bgrp * NB_B + eb;
    const int L   = slen[myb];

    const float* wp_x = wt + (kq8 * 32) * 32 + nl * 4;
    const float* hp_x = hx + (kq8 * 32) * 16 + bgq * 4;
    const float* wp_h = wt + (DD + kq8 * 32) * 32 + nl * 4;
    const float* hp_h = hx + (DD + kq8 * 32) * 16 + bgq * 4;

    float cth = 0.f;
    int p = 0;

    for (int s = 0; s < TT; ++s) {
        const uint32_t ph = (uint32_t)(s & 1);

        // warp 7: producer role. Poll all 32 peer flags + issue h(s) bulk FIRST.
        if (kq8 == 7) {
            {
                const int* fp = &g_flag[gid][lane][0];
                int v = ld_acquire(fp);
                while (v < s + 1) {
                    __nanosleep(20);
                    v = ld_acquire(fp);
                }
            }
            __syncwarp();
            if (lane == 0) {
                MBAR_EXPECT(mbh_b, 16384u);
                bulk_g2s(hx_b + (uint32_t)(DD * 16 * 4),
                         &g_hb[dir][p][bgrp][0][0], 16384u, mbh_b);
            }
        }

        mbar_wait(mbx_b, ph);               // x(s) landed

        unsigned long long acc[8];
        #pragma unroll
        for (int i = 0; i < 8; ++i) acc[i] = 0ull;

        // x-half: overlaps the in-flight h bulk + peer skew (+ co-resident block)
        gemm_phase<32>(acc, hp_x, wp_x);

        mbar_wait(mbh_b, ph);               // h(s) resident

        // h-half
        gemm_phase<32>(acc, hp_h, wp_h);

        // publish k-split partials: red[(kq8*8+nl)*2+pr][b16] as u64-pair stores
        #pragma unroll
        for (int pr = 0; pr < 2; ++pr)
            #pragma unroll
            for (int bp = 0; bp < 2; ++bp) {
                ulonglong2 v;
                v.x = acc[pr * 4 + bp * 2 + 0];
                v.y = acc[pr * 4 + bp * 2 + 1];
                *(ulonglong2*)&red[((kq8 * 8 + nl) * 2 + pr) * 16
                                   + bgq * 4 + bp * 2] = v;
            }
        __syncthreads();   // all warps done with gemm + hx regions

        // prefetch x(s+1): one bulk; overlaps epilogue + flag post + skew
        if (s + 1 < TT && tid == 0) {
            MBAR_EXPECT(mbx_b, 16384u);
            bulk_g2s(hx_b, &g_xt[dir][s + 1][bgrp][0][0], 16384u, mbx_b);
        }

        // epilogue: threads 0..127, one cell each
        float hval = 0.f;
        if (tid < 128) {
            unsigned long long s01 = 0ull, s23 = 0ull;
            #pragma unroll
            for (int q = 0; q < 8; ++q) {
                s01 = addf2(s01, red[((q * 8 + e) * 2 + 0) * 16 + eb]);
                s23 = addf2(s23, red[((q * 8 + e) * 2 + 1) * 16 + eb]);
            }
            float pi, pf, pg, po;
            unpack2(s01, pi, pf);
            unpack2(s23, pg, po);
            pi += bsv[e * 4 + 0];
            pf += bsv[e * 4 + 1];
            pg += bsv[e * 4 + 2];
            po += bsv[e * 4 + 3];

            float si = fsig(pi), sf = fsig(pf), tg = ftanh(pg), so = fsig(po);
            cth = sf * cth + si * tg;
            hval = so * ftanh(cth);

            g_hb[dir][p ^ 1][bgrp][n][eb] = hval;   // non-dup store
        }
        __syncthreads();        // all h writes done before the release-store
        if (tid == 0) st_release(&g_flag[gid][nc][0], s + 2);

        if (tid < 128 && s < L) {
            const int t = dir ? (L - 1 - s) : s;
            out[((size_t)myb * TT + t) * (2 * HH) + dir * HH + n] = hval;
        }
        p ^= 1;
    }

    // final barrier, then reset flags for the next graph replay
    global_barrier(tid);
    if (tid == 0) *((volatile int*)&g_flag[gid][nc][0]) = 0;
}

extern "C" void kernel_launch(void* const* d_in, const int* in_sizes, int n_in,
                              void* d_out, int out_size) {
    const float* x     = (const float*)d_in[0];
    const int*   lens  = (const int*)  d_in[1];
    const float* Wih_f = (const float*)d_in[2];
    const float* Whh_f = (const float*)d_in[3];
    const float* bih_f = (const float*)d_in[4];
    const float* bhh_f = (const float*)d_in[5];
    const float* Wih_b = (const float*)d_in[6];
    const float* Whh_b = (const float*)d_in[7];
    const float* bih_b = (const float*)d_in[8];
    const float* bhh_b = (const float*)d_in[9];
    float* out = (float*)d_out;

    // zero the padded/masked region (output beyond input_length must be 0)
    cudaMemsetAsync(out, 0, (size_t)out_size * sizeof(float), 0);

    const size_t smem_bytes = (size_t)SMEM_FLOATS * sizeof(float);
    cudaFuncSetAttribute(bilstm_kernel,
                         cudaFuncAttributeMaxDynamicSharedMemorySize, (int)smem_bytes);

    bilstm_kernel<<<NBLK, NTHR, smem_bytes>>>(x, lens, Wih_f, Whh_f, bih_f, bhh_f,
                                              Wih_b, Whh_b, bih_b, bhh_b, out);
}